// round 14
// baseline (speedup 1.0000x reference)
#include <cuda_runtime.h>
#include <math.h>

#define TPB   768
#define BM    4
#define S_LEN 128
#define B_TOT 512
#define H     192
#define VOC   256
#define PP    64
#define PHH   16

#define KB1   256   // folded bind1 K: [prev|pw]
#define KS1   288   // folded succ1 K: [sec|pw|phw|pad16]
#define NDS   512   // merged N: [logits 256 | selz 64 | gate1prev 192]

// output buffer offsets (floats), concatenated in reference-return order
#define OFF_LOGITS 0
#define OFF_HIDDEN (512*128*256)
#define OFF_PW     (OFF_HIDDEN + 512*128*192)
#define OFF_PHW    (OFF_PW     + 512*128*64)
#define OFF_GATE   (OFF_PHW    + 512*128*16)

__device__ float g_CB1 [KB1 * H];    // folded bind1 weights ([prev|pw] blocks)
__device__ float g_CS1 [KS1 * H];    // folded succ1 weights
__device__ float g_Esel[VOC * PP];   // emb @ sel_W_tok + sel_b
__device__ float g_Ebind[VOC * H];   // emb @ bind_W1_tok + bind_b1
__device__ float g_Wds [H * NDS];    // [dec_W | selW_prev | gate_W1_prev] columns

__device__ __forceinline__ float geluf(float x) {
    return 0.5f * x * (1.0f + erff(x * 0.7071067811865475f));
}

#define BARN(id, cnt) asm volatile("bar.sync %0, %1;" :: "r"(id), "r"(cnt) : "memory")

// ---------------------------------------------------------------------------
// prep: folded weights + vocab projections + merged weight (once per launch)
// ---------------------------------------------------------------------------
#define PREP_TOTAL (KB1*H + KS1*H + VOC*PP + VOC*H + H*NDS)

__global__ void prep_kernel(const float* __restrict__ emb,
                            const float* __restrict__ pv,
                            const float* __restrict__ pe,
                            const float* __restrict__ selW,
                            const float* __restrict__ selb,
                            const float* __restrict__ bw1,
                            const float* __restrict__ bb1,
                            const float* __restrict__ sw1,
                            const float* __restrict__ decW,
                            const float* __restrict__ gw1)
{
    int idx = blockIdx.x * blockDim.x + threadIdx.x;
    if (idx >= PREP_TOTAL) return;

    if (idx < KB1 * H) {                         // CB1: [prev(192) | pw(64)] x H
        const int row = idx / H, n = idx % H;
        float v;
        if (row < H) v = bw1[(2 * H + row) * H + n];          // prev block
        else {
            const int p = row - H;
            float a = 0.f, b = 0.f;
            for (int h = 0; h < H; h += 2) {
                a = fmaf(pv[p * H + h],     bw1[(H + h) * H + n],     a);
                b = fmaf(pv[p * H + h + 1], bw1[(H + h + 1) * H + n], b);
            }
            v = a + b;
        }
        g_CB1[row * H + n] = v;
        return;
    }
    idx -= KB1 * H;
    if (idx < KS1 * H) {                         // CS1: [sec|pw|phw|pad16]
        const int r = idx / H, n = idx % H;
        float v;
        if (r < H) v = sw1[r * H + n];
        else if (r < H + PP) {
            const int p = r - H;
            float a = 0.f, b = 0.f;
            for (int h = 0; h < H; h += 2) {
                a = fmaf(pv[p * H + h],     sw1[(H + h) * H + n],     a);
                b = fmaf(pv[p * H + h + 1], sw1[(H + h + 1) * H + n], b);
            }
            v = a + b;
        } else if (r < H + PP + PHH) {
            const int q = r - H - PP;
            float a = 0.f, b = 0.f;
            for (int h = 0; h < H; h += 2) {
                a = fmaf(pe[q * H + h],     sw1[(2 * H + h) * H + n],     a);
                b = fmaf(pe[q * H + h + 1], sw1[(2 * H + h + 1) * H + n], b);
            }
            v = a + b;
        } else v = 0.f;
        g_CS1[r * H + n] = v;
        return;
    }
    idx -= KS1 * H;
    if (idx < VOC * PP) {                        // Esel = emb @ sel_W_tok + sel_b
        const int vid = idx / PP, n = idx % PP;
        float a = 0.f, b = 0.f;
        for (int h = 0; h < H; h += 2) {
            a = fmaf(emb[vid * H + h],     selW[h * PP + n],       a);
            b = fmaf(emb[vid * H + h + 1], selW[(h + 1) * PP + n], b);
        }
        g_Esel[vid * PP + n] = a + b + selb[n];
        return;
    }
    idx -= VOC * PP;
    if (idx < VOC * H) {                         // Ebind = emb @ bind_W1_tok + bind_b1
        const int vid = idx / H, n = idx % H;
        float a = 0.f, b = 0.f;
        for (int h = 0; h < H; h += 2) {
            a = fmaf(emb[vid * H + h],     bw1[h * H + n],       a);
            b = fmaf(emb[vid * H + h + 1], bw1[(h + 1) * H + n], b);
        }
        g_Ebind[vid * H + n] = a + b + bb1[n];
        return;
    }
    idx -= VOC * H;
    {                                            // Wds: [dec_W | selW_prev | gateW1_prev]
        const int k = idx / NDS, n = idx % NDS;
        float v;
        if (n < VOC)           v = decW[k * VOC + n];
        else if (n < VOC + PP) v = selW[(H + k) * PP + (n - VOC)];    // sel prev rows [H:2H)
        else                   v = gw1[(H + k) * H + (n - VOC - PP)]; // gate1 prev rows [H:2H)
        g_Wds[k * NDS + n] = v;
    }
}

struct __align__(16) Smem {
    float red [12288];          // k-split partial scratch (max NSEG*BM*N == 12288)
    float xb_bind [BM * KB1];   // [prev | pw]
    float xb_router[BM * 384];  // [sec | prev]
    float xb_succ [BM * KS1];   // [sec | pw | phw | pad]
    float xb_dec  [BM * H];     // hidden (input to merged gemm)
    float hbuf [BM * H];        // bind1/succ1 intermediate
    float prev [BM * H];        // prev hidden (LN input)
    float succ [BM * H];        // succ (LN + gate1 input)
    float gpre [BM * H];        // prev @ gate_W1_prev (from merged gemm)
    float z64  [BM * PP];       // sel logits for the current step
    float z16  [BM * PHH];      // router logits
    float sgw2 [H];             // gate_W2 cached
    float slng [H];             // ln_g cached
    float slnb [H];             // ln_b cached
    float gdot [BM * 6];        // gate2 dot partials (6 warps per row)
    int   ids  [BM];            // ids(s)
    int   ids2 [BM];            // ids(s+1) (clamped)
};

// one-warp softmax over 64 entries; fan-out to two smem slots + global
__device__ __forceinline__ void softmax64_warp(const float* __restrict__ row, int lane,
                                               float* __restrict__ o1,
                                               float* __restrict__ o2,
                                               float* __restrict__ og)
{
    float a0 = row[lane], a1 = row[lane + 32];
    float m = fmaxf(a0, a1);
#pragma unroll
    for (int o = 16; o; o >>= 1) m = fmaxf(m, __shfl_xor_sync(0xffffffffu, m, o));
    float e0 = expf(a0 - m), e1 = expf(a1 - m);
    float sum = e0 + e1;
#pragma unroll
    for (int o = 16; o; o >>= 1) sum += __shfl_xor_sync(0xffffffffu, sum, o);
    const float inv = 1.f / sum;
    float v0 = e0 * inv, v1 = e1 * inv;
    o1[lane] = v0; o1[lane + 32] = v1;
    o2[lane] = v0; o2[lane + 32] = v1;
    og[lane] = v0; og[lane + 32] = v1;
}

// one-warp softmax over 16 entries (all 32 lanes mirror n = lane&15)
__device__ __forceinline__ void softmax16_warp(const float* __restrict__ row, int lane,
                                               float* __restrict__ o1,
                                               float* __restrict__ og)
{
    const int n = lane & 15;
    float a = row[n];
    float m = a;
#pragma unroll
    for (int o = 8; o; o >>= 1) m = fmaxf(m, __shfl_xor_sync(0xffffffffu, m, o));
    float e = expf(a - m);
    float sum = e;
#pragma unroll
    for (int o = 8; o; o >>= 1) sum += __shfl_xor_sync(0xffffffffu, sum, o);
    float v = e / sum;
    if (lane < 16) { o1[n] = v; og[n] = v; }
}

// C[BM x N] = act( X[BM x K] @ W[K x N] (+ bias | + rowbias[ids[r]] | + pre) )
// EPI: 0 normal fan-out, 1 merged dec/sel/gpre, 2 gate-dot reduce (o1 = gdot)
template<int K, int N, int ACT, bool HASB, bool ROWB, bool PREB, int EPI, typename PreF>
__device__ __forceinline__ void gemm(const float* __restrict__ xs,
                                     const float* __restrict__ W,
                                     const float* __restrict__ bias,
                                     const float* __restrict__ rbias,
                                     const int*   __restrict__ ids,
                                     const float* __restrict__ pre,
                                     const float* __restrict__ sgw2,
                                     float* __restrict__ red,
                                     PreF prefn,
                                     float* __restrict__ o1, int rs1, int off1,
                                     float* __restrict__ o2, int rs2, int off2,
                                     float* __restrict__ outg, int g_rstride)
{
    constexpr int NC4  = N / 4;
    constexpr int NSEG = TPB / NC4;
    constexpr int KS   = K / NSEG;
    static_assert(NC4 * NSEG == TPB, "thread mapping must be exact");
    static_assert(KS * NSEG == K,    "k split must be exact");
    static_assert((NSEG % 2) == 0,   "epilogue 2-acc split must be exact");
    static_assert(EPI != 2 || BM * N == TPB, "gate-dot epilogue needs 1 output/thread");

    const int t   = threadIdx.x;
    const int c4  = t % NC4;
    const int seg = t / NC4;
    const int k0  = seg * KS;
    const float4* __restrict__ Wv = reinterpret_cast<const float4*>(W);

    prefn();   // embedded pre-work for designated warps (softmax/router); others fall through

    float4 acc[BM];
#pragma unroll
    for (int r = 0; r < BM; r++) acc[r] = make_float4(0.f, 0.f, 0.f, 0.f);

    if constexpr ((KS % 4) == 0) {
        const float4* __restrict__ Xv = reinterpret_cast<const float4*>(xs);
#pragma unroll 2
        for (int kk4 = 0; kk4 < KS / 4; kk4++) {
            const int k = k0 + kk4 * 4;
            float4 xv[BM];
#pragma unroll
            for (int r = 0; r < BM; r++) xv[r] = Xv[(r * K + k) >> 2];
            float4 w0 = __ldg(&Wv[(k + 0) * NC4 + c4]);
            float4 w1 = __ldg(&Wv[(k + 1) * NC4 + c4]);
#pragma unroll
            for (int r = 0; r < BM; r++) {
                acc[r].x = fmaf(xv[r].x, w0.x, acc[r].x);
                acc[r].y = fmaf(xv[r].x, w0.y, acc[r].y);
                acc[r].z = fmaf(xv[r].x, w0.z, acc[r].z);
                acc[r].w = fmaf(xv[r].x, w0.w, acc[r].w);
                acc[r].x = fmaf(xv[r].y, w1.x, acc[r].x);
                acc[r].y = fmaf(xv[r].y, w1.y, acc[r].y);
                acc[r].z = fmaf(xv[r].y, w1.z, acc[r].z);
                acc[r].w = fmaf(xv[r].y, w1.w, acc[r].w);
            }
            float4 w2 = __ldg(&Wv[(k + 2) * NC4 + c4]);
            float4 w3 = __ldg(&Wv[(k + 3) * NC4 + c4]);
#pragma unroll
            for (int r = 0; r < BM; r++) {
                acc[r].x = fmaf(xv[r].z, w2.x, acc[r].x);
                acc[r].y = fmaf(xv[r].z, w2.y, acc[r].y);
                acc[r].z = fmaf(xv[r].z, w2.z, acc[r].z);
                acc[r].w = fmaf(xv[r].z, w2.w, acc[r].w);
                acc[r].x = fmaf(xv[r].w, w3.x, acc[r].x);
                acc[r].y = fmaf(xv[r].w, w3.y, acc[r].y);
                acc[r].z = fmaf(xv[r].w, w3.z, acc[r].z);
                acc[r].w = fmaf(xv[r].w, w3.w, acc[r].w);
            }
        }
    } else {
        const float2* __restrict__ Xv = reinterpret_cast<const float2*>(xs);
#pragma unroll 3
        for (int kk2 = 0; kk2 < KS / 2; kk2++) {
            const int k = k0 + kk2 * 2;
            float2 xv[BM];
#pragma unroll
            for (int r = 0; r < BM; r++) xv[r] = Xv[(r * K + k) >> 1];
            float4 w0 = __ldg(&Wv[(k + 0) * NC4 + c4]);
            float4 w1 = __ldg(&Wv[(k + 1) * NC4 + c4]);
#pragma unroll
            for (int r = 0; r < BM; r++) {
                acc[r].x = fmaf(xv[r].x, w0.x, acc[r].x);
                acc[r].y = fmaf(xv[r].x, w0.y, acc[r].y);
                acc[r].z = fmaf(xv[r].x, w0.z, acc[r].z);
                acc[r].w = fmaf(xv[r].x, w0.w, acc[r].w);
                acc[r].x = fmaf(xv[r].y, w1.x, acc[r].x);
                acc[r].y = fmaf(xv[r].y, w1.y, acc[r].y);
                acc[r].z = fmaf(xv[r].y, w1.z, acc[r].z);
                acc[r].w = fmaf(xv[r].y, w1.w, acc[r].w);
            }
        }
    }

    float4* redv = reinterpret_cast<float4*>(red);
#pragma unroll
    for (int r = 0; r < BM; r++) redv[(seg * BM + r) * NC4 + c4] = acc[r];
    __syncthreads();

    for (int i = t; i < BM * N; i += TPB) {
        const int r = i / N;
        const int n = i % N;
        float v;
        if constexpr ((NSEG % 4) == 0) {
            float v0 = 0.f, v1 = 0.f, v2 = 0.f, v3 = 0.f;
#pragma unroll
            for (int g = 0; g < NSEG; g += 4) {
                v0 += red[((g + 0) * BM + r) * N + n];
                v1 += red[((g + 1) * BM + r) * N + n];
                v2 += red[((g + 2) * BM + r) * N + n];
                v3 += red[((g + 3) * BM + r) * N + n];
            }
            v = (v0 + v1) + (v2 + v3);
        } else {
            float v0 = 0.f, v1 = 0.f;
#pragma unroll
            for (int g = 0; g < NSEG; g += 2) {
                v0 += red[((g + 0) * BM + r) * N + n];
                v1 += red[((g + 1) * BM + r) * N + n];
            }
            v = v0 + v1;
        }
        if constexpr (EPI == 1) {
            if (n < VOC) {
                outg[r * g_rstride + n] = v;
            } else if (n < VOC + PP) {
                const int nn = n - VOC;
                o1[r * PP + nn] = v + __ldg(&rbias[ids[r] * PP + nn]);
            } else {
                o2[r * H + (n - VOC - PP)] = v;
            }
        } else {
            if (HASB) v += __ldg(&bias[n]);
            if (ROWB) v += __ldg(&rbias[ids[r] * N + n]);
            if (PREB) v += pre[r * N + n];
            if (ACT == 1) v = geluf(v);
            if (ACT == 2) v = tanhf(v);
            if constexpr (EPI == 2) {
                // gate2 dot: per-warp reduce contributions, lane0 writes partial
                float contrib = v * sgw2[n];
#pragma unroll
                for (int o = 16; o; o >>= 1)
                    contrib += __shfl_xor_sync(0xffffffffu, contrib, o);
                if ((t & 31) == 0) o1[r * 6 + ((t >> 5) % 6)] = contrib;
            } else {
                if (o1) o1[r * rs1 + off1 + n] = v;
                if (o2) o2[r * rs2 + off2 + n] = v;
                if (outg) outg[r * g_rstride + n] = v;
            }
        }
    }
    __syncthreads();
}

struct NoPre { __device__ void operator()() const {} };

__global__ void __launch_bounds__(TPB, 1)
spike_kernel(const int* __restrict__ ids_g,
             const float* __restrict__ bind_W2,  const float* __restrict__ bind_b2,
             const float* __restrict__ router_W, const float* __restrict__ router_b,
             const float* __restrict__ succ_b1,
             const float* __restrict__ succ_W2,  const float* __restrict__ succ_b2,
             const float* __restrict__ gate_W1,  const float* __restrict__ gate_b1,
             const float* __restrict__ gate_W2,  const float* __restrict__ gate_b2,
             const float* __restrict__ ln_g,     const float* __restrict__ ln_b,
             float* __restrict__ out)
{
    __shared__ Smem sm;
    const int t    = threadIdx.x;
    const int lane = t & 31;
    const int b0   = blockIdx.x * BM;

    float* out_logits = out + OFF_LOGITS;
    float* out_hidden = out + OFF_HIDDEN;
    float* out_pw     = out + OFF_PW;
    float* out_phw    = out + OFF_PHW;
    float* out_gate   = out + OFF_GATE;

    // init: zero prev/gpre, succ pad; z64(0) = E_sel[id(0)]; cache small vectors
    {
        const int r = t / H, h = t % H;
        sm.prev[t] = 0.f;
        sm.gpre[t] = 0.f;
        sm.xb_bind  [r * KB1 + h] = 0.f;       // prev slot of bind input
        sm.xb_router[r * 384 + H + h] = 0.f;
        if (t < H) {
            sm.sgw2[t] = __ldg(&gate_W2[t]);
            sm.slng[t] = __ldg(&ln_g[t]);
            sm.slnb[t] = __ldg(&ln_b[t]);
        }
        if (t < BM * 16) {                      // pad slots [272:288) of xb_succ
            const int rr = t / 16, i = t % 16;
            sm.xb_succ[rr * KS1 + 272 + i] = 0.f;
        }
        if (t < BM * PP) {                      // z64(0): prev=0 -> token term only
            const int rr = t / PP, n = t % PP;
            const int id0 = __ldg(&ids_g[(b0 + rr) * S_LEN + 0]);
            sm.z64[t] = __ldg(&g_Esel[id0 * PP + n]);
        }
    }
    __syncthreads();

    for (int s = 0; s < S_LEN; s++) {
        // stage ids(s) and ids(s+1); consumed after later barriers
        if (t < BM) {
            sm.ids [t] = __ldg(&ids_g[(b0 + t) * S_LEN + s]);
            const int s1 = (s + 1 < S_LEN) ? s + 1 : S_LEN - 1;
            sm.ids2[t] = __ldg(&ids_g[(b0 + t) * S_LEN + s1]);
        }

        // --- phase A: bind1 with EMBEDDED softmax(pw) ---
        // warps 18-23 own k in [192,256) == the pw region; warps 18-21 compute
        // softmax rows 0-3 first, named-bar with 22-23, then all six join the
        // mainloop. Warps 0-17 (k < 192 == prev region) start immediately.
        auto preA = [&]() {
            if (t >= 576) {
                const int w = (t - 576) >> 5;
                if (w < BM)
                    softmax64_warp(sm.z64 + w * PP, lane,
                                   sm.xb_bind + w * KB1 + H,
                                   sm.xb_succ + w * KS1 + H,
                                   out_pw + ((b0 + w) * S_LEN + s) * PP);
                BARN(3, 192);
            }
        };
        gemm<KB1, H, 1, false, true, false, 0>(sm.xb_bind, g_CB1, nullptr, g_Ebind, sm.ids,
                                               nullptr, nullptr, sm.red, preA,
                                               sm.hbuf, H, 0, nullptr, 0, 0, nullptr, 0);

        // --- phase B: bind2 -> sec ---
        gemm<H, H, 2, true, false, false, 0>(sm.hbuf, bind_W2, bind_b2, nullptr, nullptr,
                                             nullptr, nullptr, sm.red, NoPre(),
                                             sm.xb_router, 384, 0, sm.xb_succ, KS1, 0,
                                             nullptr, 0);

        // --- phase C: succ1 with EMBEDDED router + softmax(phw) ---
        // warps 16-23: mini-gemm z16 = [sec,prev] @ router_W + b (4-way k-split,
        // quad shuffle reduce), bar, softmax rows by warps 16-19, bar, then their
        // succ1 chunks (which include the phw region). Warps 0-15: k < 198 uses
        // only sec|pw (ready) — start immediately.
        auto preC = [&]() {
            if (t >= 512) {
                const int t2  = t - 512;            // 0..255
                const int idx = t2 >> 2;            // 0..63 -> (row, col)
                const int rr  = idx >> 4, nn = idx & 15;
                const int q   = t2 & 3;             // k quarter
                const float* xr = sm.xb_router + rr * 384;
                float a = 0.f, b = 0.f;
                const int kq = q * 96;
#pragma unroll 8
                for (int k = 0; k < 96; k += 2) {
                    a = fmaf(xr[kq + k],     __ldg(&router_W[(kq + k) * PHH + nn]),     a);
                    b = fmaf(xr[kq + k + 1], __ldg(&router_W[(kq + k + 1) * PHH + nn]), b);
                }
                float acc = a + b;
                acc += __shfl_xor_sync(0xffffffffu, acc, 1);
                acc += __shfl_xor_sync(0xffffffffu, acc, 2);
                if (q == 0) sm.z16[rr * PHH + nn] = acc + __ldg(&router_b[nn]);
                BARN(4, 256);
                const int w = t2 >> 5;              // 0..7
                if (w < BM)
                    softmax16_warp(sm.z16 + w * PHH, lane,
                                   sm.xb_succ + w * KS1 + H + PP,
                                   out_phw + ((b0 + w) * S_LEN + s) * PHH);
                BARN(5, 256);
            }
        };
        gemm<KS1, H, 1, true, false, false, 0>(sm.xb_succ, g_CS1, succ_b1, nullptr, nullptr,
                                               nullptr, nullptr, sm.red, preC,
                                               sm.hbuf, H, 0, nullptr, 0, 0, nullptr, 0);

        // --- phase D: succ2 -> succ ---
        gemm<H, H, 2, true, false, false, 0>(sm.hbuf, succ_W2, succ_b2, nullptr, nullptr,
                                             nullptr, nullptr, sm.red, NoPre(),
                                             sm.succ, H, 0, nullptr, 0, 0, nullptr, 0);

        // --- phase E: gate1 (prev part folded) with EMBEDDED gate2 dot ---
        gemm<H, H, 1, true, false, true, 2>(sm.succ, gate_W1, gate_b1, nullptr, nullptr,
                                            sm.gpre, sm.sgw2, sm.red, NoPre(),
                                            sm.gdot, 0, 0, nullptr, 0, 0, nullptr, 0);

        // --- phase F: sigmoid gate + hidden mix + layernorm + fan-out (4 warps) ---
        {
            const int w = t >> 5;
            if (w < BM) {
                float v = ((sm.gdot[w * 6 + 0] + sm.gdot[w * 6 + 1]) +
                           (sm.gdot[w * 6 + 2] + sm.gdot[w * 6 + 3])) +
                          (sm.gdot[w * 6 + 4] + sm.gdot[w * 6 + 5]) + __ldg(&gate_b2[0]);
                const float g = 1.f / (1.f + expf(-v));
                if (lane == 0) out_gate[(b0 + w) * S_LEN + s] = g;

                float lv[H / 32];
                float mean = 0.f;
#pragma unroll
                for (int i = 0; i < H / 32; i++) {
                    const int h = lane + 32 * i;
                    float hv = g * sm.succ[w * H + h] + (1.f - g) * sm.prev[w * H + h];
                    lv[i] = hv; mean += hv;
                }
#pragma unroll
                for (int o = 16; o; o >>= 1) mean += __shfl_xor_sync(0xffffffffu, mean, o);
                mean *= (1.f / (float)H);
                float var = 0.f;
#pragma unroll
                for (int i = 0; i < H / 32; i++) { float d = lv[i] - mean; var = fmaf(d, d, var); }
#pragma unroll
                for (int o = 16; o; o >>= 1) var += __shfl_xor_sync(0xffffffffu, var, o);
                var *= (1.f / (float)H);
                const float rstd = rsqrtf(var + 1e-5f);
                float* oh = out_hidden + ((b0 + w) * S_LEN + s) * H;
#pragma unroll
                for (int i = 0; i < H / 32; i++) {
                    const int h = lane + 32 * i;
                    float o = (lv[i] - mean) * rstd * sm.slng[h] + sm.slnb[h];
                    sm.prev[w * H + h] = o;
                    sm.xb_dec[w * H + h] = o;
                    sm.xb_bind  [w * KB1 + h] = o;       // prev slot
                    sm.xb_router[w * 384 + H + h] = o;
                    oh[h] = o;
                }
            }
        }
        __syncthreads();

        // --- phase G: merged readout + next-step selector + next gate1 prev-part ---
        gemm<H, NDS, 0, false, false, false, 1>(sm.xb_dec, g_Wds, nullptr, g_Esel, sm.ids2,
                                                nullptr, nullptr, sm.red, NoPre(),
                                                sm.z64, 0, 0, sm.gpre, 0, 0,
                                                out_logits + (b0 * S_LEN + s) * VOC, S_LEN * VOC);
    }
}

extern "C" void kernel_launch(void* const* d_in, const int* in_sizes, int n_in,
                              void* d_out, int out_size)
{
    const int*   ids          = (const int*)  d_in[0];
    const float* emb          = (const float*)d_in[1];
    const float* sel_W        = (const float*)d_in[2];
    const float* sel_b        = (const float*)d_in[3];
    const float* patch_values = (const float*)d_in[4];
    const float* bind_W1      = (const float*)d_in[5];
    const float* bind_b1      = (const float*)d_in[6];
    const float* bind_W2      = (const float*)d_in[7];
    const float* bind_b2      = (const float*)d_in[8];
    const float* phase_embed  = (const float*)d_in[9];
    const float* router_W     = (const float*)d_in[10];
    const float* router_b     = (const float*)d_in[11];
    const float* succ_W1      = (const float*)d_in[12];
    const float* succ_b1      = (const float*)d_in[13];
    const float* succ_W2      = (const float*)d_in[14];
    const float* succ_b2      = (const float*)d_in[15];
    const float* gate_W1      = (const float*)d_in[16];
    const float* gate_b1      = (const float*)d_in[17];
    const float* gate_W2      = (const float*)d_in[18];
    const float* gate_b2      = (const float*)d_in[19];
    const float* ln_g         = (const float*)d_in[20];
    const float* ln_b         = (const float*)d_in[21];
    const float* dec_W        = (const float*)d_in[22];

    prep_kernel<<<(PREP_TOTAL + 255) / 256, 256>>>(emb, patch_values, phase_embed,
                                                   sel_W, sel_b, bind_W1, bind_b1, succ_W1,
                                                   dec_W, gate_W1);

    spike_kernel<<<B_TOT / BM, TPB>>>(
        ids,
        bind_W2, bind_b2,
        router_W, router_b,
        succ_b1, succ_W2, succ_b2,
        gate_W1, gate_b1, gate_W2, gate_b2,
        ln_g, ln_b, (float*)d_out);
}

// round 15
// speedup vs baseline: 1.1368x; 1.1368x over previous
#include <cuda_runtime.h>
#include <math.h>

#define TPB   768
#define BM    4
#define S_LEN 128
#define B_TOT 512
#define H     192
#define VOC   256
#define PP    64
#define PHH   16

#define KB1   256   // folded bind1 K: [prev|pw]           (tok folded into E_bind)
#define KS1   320   // folded succ1 K: [sec|pw|phw|pad48]

// output buffer offsets (floats), concatenated in reference-return order
#define OFF_LOGITS 0
#define OFF_HIDDEN (512*128*256)
#define OFF_PW     (OFF_HIDDEN + 512*128*192)
#define OFF_PHW    (OFF_PW     + 512*128*64)
#define OFF_GATE   (OFF_PHW    + 512*128*16)

__device__ float g_CB1 [KB1 * H];   // folded bind1 weights ([prev|pw] blocks)
__device__ float g_CS1 [KS1 * H];   // folded succ1 weights
__device__ float g_Esel[VOC * PP];  // emb @ sel_W_tok + sel_b
__device__ float g_Ebind[VOC * H];  // emb @ bind_W1_tok + bind_b1

__device__ __forceinline__ float geluf(float x) {
    return 0.5f * x * (1.0f + erff(x * 0.7071067811865475f));
}

// ---------------------------------------------------------------------------
// prep: build folded weights + per-vocab token projections (once per launch)
// ---------------------------------------------------------------------------
#define PREP_TOTAL (KB1*H + KS1*H + VOC*PP + VOC*H)

__global__ void prep_kernel(const float* __restrict__ emb,
                            const float* __restrict__ pv,
                            const float* __restrict__ pe,
                            const float* __restrict__ selW,
                            const float* __restrict__ selb,
                            const float* __restrict__ bw1,
                            const float* __restrict__ bb1,
                            const float* __restrict__ sw1)
{
    int idx = blockIdx.x * blockDim.x + threadIdx.x;
    if (idx >= PREP_TOTAL) return;

    if (idx < KB1 * H) {                         // CB1: [prev(192) | pw(64)] x H
        const int row = idx / H, n = idx % H;
        float v;
        if (row < H) v = bw1[(2 * H + row) * H + n];          // prev block
        else {
            const int p = row - H;
            float a = 0.f, b = 0.f;
            for (int h = 0; h < H; h += 2) {
                a = fmaf(pv[p * H + h],     bw1[(H + h) * H + n],     a);
                b = fmaf(pv[p * H + h + 1], bw1[(H + h + 1) * H + n], b);
            }
            v = a + b;
        }
        g_CB1[row * H + n] = v;
        return;
    }
    idx -= KB1 * H;
    if (idx < KS1 * H) {                         // CS1: [sec|pw|phw|pad]
        const int r = idx / H, n = idx % H;
        float v;
        if (r < H) v = sw1[r * H + n];
        else if (r < H + PP) {
            const int p = r - H;
            float a = 0.f, b = 0.f;
            for (int h = 0; h < H; h += 2) {
                a = fmaf(pv[p * H + h],     sw1[(H + h) * H + n],     a);
                b = fmaf(pv[p * H + h + 1], sw1[(H + h + 1) * H + n], b);
            }
            v = a + b;
        } else if (r < H + PP + PHH) {
            const int q = r - H - PP;
            float a = 0.f, b = 0.f;
            for (int h = 0; h < H; h += 2) {
                a = fmaf(pe[q * H + h],     sw1[(2 * H + h) * H + n],     a);
                b = fmaf(pe[q * H + h + 1], sw1[(2 * H + h + 1) * H + n], b);
            }
            v = a + b;
        } else v = 0.f;
        g_CS1[r * H + n] = v;
        return;
    }
    idx -= KS1 * H;
    if (idx < VOC * PP) {                        // Esel = emb @ sel_W_tok + sel_b
        const int vid = idx / PP, n = idx % PP;
        float a = 0.f, b = 0.f;
        for (int h = 0; h < H; h += 2) {
            a = fmaf(emb[vid * H + h],     selW[h * PP + n],       a);
            b = fmaf(emb[vid * H + h + 1], selW[(h + 1) * PP + n], b);
        }
        g_Esel[vid * PP + n] = a + b + selb[n];
        return;
    }
    idx -= VOC * PP;
    {                                            // Ebind = emb @ bind_W1_tok + bind_b1
        const int vid = idx / H, n = idx % H;
        float a = 0.f, b = 0.f;
        for (int h = 0; h < H; h += 2) {
            a = fmaf(emb[vid * H + h],     bw1[h * H + n],       a);
            b = fmaf(emb[vid * H + h + 1], bw1[(h + 1) * H + n], b);
        }
        g_Ebind[vid * H + n] = a + b + bb1[n];
    }
}

struct __align__(16) Smem {
    float red [12288];          // k-split partial scratch: NSEG*BM*N == 12288 for all shapes
    float xb_bind [BM * KB1];   // [prev | pw]
    float xb_router[BM * 384];  // [sec | prev]
    float xb_succ [BM * KS1];   // [sec | pw | phw | pad]
    float xb_gate [BM * 384];   // [succ | prev]
    float xb_dec  [BM * H];     // hidden (also sel input)
    float hbuf [BM * H];        // bind1/succ1/gate1 intermediate
    float prev [BM * H];        // normal copy for LN
    float succ [BM * H];        // normal copy for LN
    float z64  [BM * PP];
    float z16  [BM * PHH];
    float sgw2 [H];             // gate_W2 cached in smem
    float slng [H];             // ln_g cached
    float slnb [H];             // ln_b cached
    int   ids  [BM];            // ids(s)
};

// C[BM x N] = act( X[BM x K] @ W[K x N] (+ bias | + rowbias[ids[r]]) )
// thread -> (col4 = t % (N/4), kseg = t / (N/4)); partials reduced through smem.
// ACT: 0 = none, 1 = gelu(exact), 2 = tanh
template<int K, int N, int ACT, bool HASB, bool ROWB>
__device__ __forceinline__ void gemm(const float* __restrict__ xs,
                                     const float* __restrict__ W,
                                     const float* __restrict__ bias,
                                     const float* __restrict__ rbias,
                                     const int*   __restrict__ ids,
                                     float* __restrict__ red,
                                     float* __restrict__ o1, int rs1, int off1,
                                     float* __restrict__ o2, int rs2, int off2,
                                     float* __restrict__ outg, int g_rstride)
{
    constexpr int NC4  = N / 4;
    constexpr int NSEG = TPB / NC4;
    constexpr int KS   = K / NSEG;
    static_assert(NC4 * NSEG == TPB, "thread mapping must be exact");
    static_assert(KS * NSEG == K,    "k split must be exact");
    static_assert((NSEG % 2) == 0,   "epilogue 2-acc split must be exact");

    const int t   = threadIdx.x;
    const int c4  = t % NC4;
    const int seg = t / NC4;
    const float4* __restrict__ Wv = reinterpret_cast<const float4*>(W);

    float4 acc[BM];
#pragma unroll
    for (int r = 0; r < BM; r++) acc[r] = make_float4(0.f, 0.f, 0.f, 0.f);

    const int k0 = seg * KS;

    if constexpr ((KS % 4) == 0) {
        const float4* __restrict__ Xv = reinterpret_cast<const float4*>(xs);
#pragma unroll 2
        for (int kk4 = 0; kk4 < KS / 4; kk4++) {
            const int k = k0 + kk4 * 4;
            float4 xv[BM];
#pragma unroll
            for (int r = 0; r < BM; r++) xv[r] = Xv[(r * K + k) >> 2];
            // all four weight loads issued up front -> deeper MLP on the LDG stream
            float4 w0 = __ldg(&Wv[(k + 0) * NC4 + c4]);
            float4 w1 = __ldg(&Wv[(k + 1) * NC4 + c4]);
            float4 w2 = __ldg(&Wv[(k + 2) * NC4 + c4]);
            float4 w3 = __ldg(&Wv[(k + 3) * NC4 + c4]);
#pragma unroll
            for (int r = 0; r < BM; r++) {
                acc[r].x = fmaf(xv[r].x, w0.x, acc[r].x);
                acc[r].y = fmaf(xv[r].x, w0.y, acc[r].y);
                acc[r].z = fmaf(xv[r].x, w0.z, acc[r].z);
                acc[r].w = fmaf(xv[r].x, w0.w, acc[r].w);
                acc[r].x = fmaf(xv[r].y, w1.x, acc[r].x);
                acc[r].y = fmaf(xv[r].y, w1.y, acc[r].y);
                acc[r].z = fmaf(xv[r].y, w1.z, acc[r].z);
                acc[r].w = fmaf(xv[r].y, w1.w, acc[r].w);
            }
#pragma unroll
            for (int r = 0; r < BM; r++) {
                acc[r].x = fmaf(xv[r].z, w2.x, acc[r].x);
                acc[r].y = fmaf(xv[r].z, w2.y, acc[r].y);
                acc[r].z = fmaf(xv[r].z, w2.z, acc[r].z);
                acc[r].w = fmaf(xv[r].z, w2.w, acc[r].w);
                acc[r].x = fmaf(xv[r].w, w3.x, acc[r].x);
                acc[r].y = fmaf(xv[r].w, w3.y, acc[r].y);
                acc[r].z = fmaf(xv[r].w, w3.z, acc[r].z);
                acc[r].w = fmaf(xv[r].w, w3.w, acc[r].w);
            }
        }
    } else {
#pragma unroll
        for (int kk = 0; kk < KS; kk++) {
            const int k = k0 + kk;
            float4 w = __ldg(&Wv[k * NC4 + c4]);
#pragma unroll
            for (int r = 0; r < BM; r++) {
                float x = xs[r * K + k];
                acc[r].x = fmaf(x, w.x, acc[r].x);
                acc[r].y = fmaf(x, w.y, acc[r].y);
                acc[r].z = fmaf(x, w.z, acc[r].z);
                acc[r].w = fmaf(x, w.w, acc[r].w);
            }
        }
    }

    float4* redv = reinterpret_cast<float4*>(red);
#pragma unroll
    for (int r = 0; r < BM; r++) redv[(seg * BM + r) * NC4 + c4] = acc[r];
    __syncthreads();

    for (int i = t; i < BM * N; i += TPB) {
        const int r = i / N;
        const int n = i % N;
        float v;
        if constexpr ((NSEG % 4) == 0) {
            float v0 = 0.f, v1 = 0.f, v2 = 0.f, v3 = 0.f;
#pragma unroll
            for (int g = 0; g < NSEG; g += 4) {
                v0 += red[((g + 0) * BM + r) * N + n];
                v1 += red[((g + 1) * BM + r) * N + n];
                v2 += red[((g + 2) * BM + r) * N + n];
                v3 += red[((g + 3) * BM + r) * N + n];
            }
            v = (v0 + v1) + (v2 + v3);
        } else {
            float v0 = 0.f, v1 = 0.f;
#pragma unroll
            for (int g = 0; g < NSEG; g += 2) {
                v0 += red[((g + 0) * BM + r) * N + n];
                v1 += red[((g + 1) * BM + r) * N + n];
            }
            v = v0 + v1;
        }
        if (HASB) v += __ldg(&bias[n]);
        if (ROWB) v += __ldg(&rbias[ids[r] * N + n]);
        if (ACT == 1) v = geluf(v);
        if (ACT == 2) v = tanhf(v);
        if (o1) o1[r * rs1 + off1 + n] = v;
        if (o2) o2[r * rs2 + off2 + n] = v;
        if (outg) outg[r * g_rstride + n] = v;
    }
    __syncthreads();
}

// warp-per-row softmax over N (<= 64): fan-out to two smem slots + global
template<int N>
__device__ __forceinline__ void softmax_rows(const float* __restrict__ z,
                                             float* __restrict__ o1, int rs1, int off1,
                                             float* __restrict__ o2, int rs2, int off2,
                                             float* __restrict__ outg, int g_rstride)
{
    const int w = threadIdx.x >> 5, lane = threadIdx.x & 31;
    if (w < BM) {
        const float* row = z + w * N;
        constexpr int PER = (N + 31) / 32;
        float m = -3.0e38f;
#pragma unroll
        for (int i = 0; i < PER; i++) {
            int n = lane + 32 * i;
            if (n < N) m = fmaxf(m, row[n]);
        }
#pragma unroll
        for (int o = 16; o; o >>= 1) m = fmaxf(m, __shfl_xor_sync(0xffffffffu, m, o));
        float ev[PER];
        float sum = 0.f;
#pragma unroll
        for (int i = 0; i < PER; i++) {
            int n = lane + 32 * i;
            if (n < N) { ev[i] = expf(row[n] - m); sum += ev[i]; }
        }
#pragma unroll
        for (int o = 16; o; o >>= 1) sum += __shfl_xor_sync(0xffffffffu, sum, o);
        const float inv = 1.f / sum;
#pragma unroll
        for (int i = 0; i < PER; i++) {
            int n = lane + 32 * i;
            if (n < N) {
                float v = ev[i] * inv;
                o1[w * rs1 + off1 + n] = v;
                o2[w * rs2 + off2 + n] = v;
                outg[w * g_rstride + n] = v;
            }
        }
    }
}

__global__ void __launch_bounds__(TPB, 1)
spike_kernel(const int* __restrict__ ids_g,
             const float* __restrict__ selW_prev,            // sel_W rows [H:2H)
             const float* __restrict__ bind_W2,  const float* __restrict__ bind_b2,
             const float* __restrict__ router_W, const float* __restrict__ router_b,
             const float* __restrict__ succ_b1,
             const float* __restrict__ succ_W2,  const float* __restrict__ succ_b2,
             const float* __restrict__ gate_W1,  const float* __restrict__ gate_b1,
             const float* __restrict__ gate_W2,  const float* __restrict__ gate_b2,
             const float* __restrict__ ln_g,     const float* __restrict__ ln_b,
             const float* __restrict__ dec_W,
             float* __restrict__ out)
{
    __shared__ Smem sm;
    const int t  = threadIdx.x;
    const int b0 = blockIdx.x * BM;

    float* out_logits = out + OFF_LOGITS;
    float* out_hidden = out + OFF_HIDDEN;
    float* out_pw     = out + OFF_PW;
    float* out_phw    = out + OFF_PHW;
    float* out_gate   = out + OFF_GATE;

    // zero prev slots + hidden + succ1 pad ; cache small vectors
    {
        const int r = t / H, h = t % H;
        sm.prev[t] = 0.f;
        sm.xb_dec[t] = 0.f;
        sm.xb_bind  [r * KB1 + h] = 0.f;       // prev slot of bind input
        sm.xb_router[r * 384 + H + h] = 0.f;
        sm.xb_gate  [r * 384 + H + h] = 0.f;
        if (t < H) {
            sm.sgw2[t] = __ldg(&gate_W2[t]);
            sm.slng[t] = __ldg(&ln_g[t]);
            sm.slnb[t] = __ldg(&ln_b[t]);
        }
        if (t < BM * 48) {                      // pad slots [272:320) of xb_succ
            const int rr = t / 48, i = t % 48;
            sm.xb_succ[rr * KS1 + 272 + i] = 0.f;
        }
    }
    __syncthreads();

    for (int s = 0; s < S_LEN; s++) {
        // stage ids(s); published by the sel gemm's internal barrier
        if (t < BM) sm.ids[t] = __ldg(&ids_g[(b0 + t) * S_LEN + s]);

        // patch selector (tok folded): pw = softmax(prev @ selW_prev + E_sel[id])
        gemm<H, PP, 0, false, true>(sm.xb_dec, selW_prev, nullptr, g_Esel, sm.ids, sm.red,
                                    sm.z64, PP, 0, nullptr, 0, 0, nullptr, 0);
        softmax_rows<PP>(sm.z64,
                         sm.xb_bind, KB1, H,         // pw slot of bind1 input
                         sm.xb_succ, KS1, H,         // pw slot of succ1 input
                         out_pw + (b0 * S_LEN + s) * PP, S_LEN * PP);
        __syncthreads();

        // section binder (tok+patch folded): tanh(gelu([prev,pw]@CB1 + E_bind[id]) @ W2 + b2) -> sec
        gemm<KB1, H, 1, false, true>(sm.xb_bind, g_CB1, nullptr, g_Ebind, sm.ids, sm.red,
                                     sm.hbuf, H, 0, nullptr, 0, 0, nullptr, 0);
        gemm<H, H, 2, true, false>(sm.hbuf, bind_W2, bind_b2, nullptr, nullptr, sm.red,
                                   sm.xb_router, 384, 0, sm.xb_succ, KS1, 0, nullptr, 0);

        // phase routing: phw = softmax([sec,prev] @ router_W + b)
        gemm<384, PHH, 0, true, false>(sm.xb_router, router_W, router_b, nullptr, nullptr, sm.red,
                                       sm.z16, PHH, 0, nullptr, 0, 0, nullptr, 0);
        softmax_rows<PHH>(sm.z16,
                          sm.xb_succ, KS1, H + PP,   // phw slot of succ1 input
                          sm.z16, PHH, 0,            // harmless self-write (keeps fan-out shape)
                          out_phw + (b0 * S_LEN + s) * PHH, S_LEN * PHH);
        __syncthreads();

        // successor (patch+phase folded): tanh(gelu([sec,pw,phw,0] @ CS1 + b1) @ W2 + b2) -> succ
        gemm<KS1, H, 1, true, false>(sm.xb_succ, g_CS1, succ_b1, nullptr, nullptr, sm.red,
                                     sm.hbuf, H, 0, nullptr, 0, 0, nullptr, 0);
        gemm<H, H, 2, true, false>(sm.hbuf, succ_W2, succ_b2, nullptr, nullptr, sm.red,
                                   sm.xb_gate, 384, 0, sm.succ, H, 0, nullptr, 0);

        // gate hidden layer: gelu([succ,prev] @ gW1 + b1)
        gemm<384, H, 1, true, false>(sm.xb_gate, gate_W1, gate_b1, nullptr, nullptr, sm.red,
                                     sm.hbuf, H, 0, nullptr, 0, 0, nullptr, 0);

        // fused: gate2 dot + sigmoid + hidden mix + layernorm + fan-out (4 warps)
        {
            const int w = t >> 5, lane = t & 31;
            if (w < BM) {
                float v = 0.f;
#pragma unroll
                for (int i = 0; i < H / 32; i++) {
                    const int k = lane + 32 * i;
                    v = fmaf(sm.hbuf[w * H + k], sm.sgw2[k], v);
                }
#pragma unroll
                for (int o = 16; o; o >>= 1) v += __shfl_xor_sync(0xffffffffu, v, o);
                v += gate_b2[0];
                const float g = 1.f / (1.f + expf(-v));
                if (lane == 0) out_gate[(b0 + w) * S_LEN + s] = g;

                float lv[H / 32];
                float mean = 0.f;
#pragma unroll
                for (int i = 0; i < H / 32; i++) {
                    const int h = lane + 32 * i;
                    float hv = g * sm.succ[w * H + h] + (1.f - g) * sm.prev[w * H + h];
                    lv[i] = hv; mean += hv;
                }
#pragma unroll
                for (int o = 16; o; o >>= 1) mean += __shfl_xor_sync(0xffffffffu, mean, o);
                mean *= (1.f / (float)H);
                float var = 0.f;
#pragma unroll
                for (int i = 0; i < H / 32; i++) { float d = lv[i] - mean; var = fmaf(d, d, var); }
#pragma unroll
                for (int o = 16; o; o >>= 1) var += __shfl_xor_sync(0xffffffffu, var, o);
                var *= (1.f / (float)H);
                const float rstd = rsqrtf(var + 1e-5f);
                float* oh = out_hidden + ((b0 + w) * S_LEN + s) * H;
#pragma unroll
                for (int i = 0; i < H / 32; i++) {
                    const int h = lane + 32 * i;
                    float o = (lv[i] - mean) * rstd * sm.slng[h] + sm.slnb[h];
                    sm.prev[w * H + h] = o;
                    sm.xb_dec[w * H + h] = o;
                    sm.xb_bind  [w * KB1 + h] = o;       // prev slot
                    sm.xb_router[w * 384 + H + h] = o;
                    sm.xb_gate  [w * 384 + H + h] = o;
                    oh[h] = o;
                }
            }
        }
        __syncthreads();

        // readout: logits = hidden @ dec_W
        gemm<H, VOC, 0, false, false>(sm.xb_dec, dec_W, nullptr, nullptr, nullptr, sm.red,
                                      nullptr, 0, 0, nullptr, 0, 0,
                                      out_logits + (b0 * S_LEN + s) * VOC, S_LEN * VOC);
    }
}

extern "C" void kernel_launch(void* const* d_in, const int* in_sizes, int n_in,
                              void* d_out, int out_size)
{
    const int*   ids          = (const int*)  d_in[0];
    const float* emb          = (const float*)d_in[1];
    const float* sel_W        = (const float*)d_in[2];
    const float* sel_b        = (const float*)d_in[3];
    const float* patch_values = (const float*)d_in[4];
    const float* bind_W1      = (const float*)d_in[5];
    const float* bind_b1      = (const float*)d_in[6];
    const float* bind_W2      = (const float*)d_in[7];
    const float* bind_b2      = (const float*)d_in[8];
    const float* phase_embed  = (const float*)d_in[9];
    const float* router_W     = (const float*)d_in[10];
    const float* router_b     = (const float*)d_in[11];
    const float* succ_W1      = (const float*)d_in[12];
    const float* succ_b1      = (const float*)d_in[13];
    const float* succ_W2      = (const float*)d_in[14];
    const float* succ_b2      = (const float*)d_in[15];
    const float* gate_W1      = (const float*)d_in[16];
    const float* gate_b1      = (const float*)d_in[17];
    const float* gate_W2      = (const float*)d_in[18];
    const float* gate_b2      = (const float*)d_in[19];
    const float* ln_g         = (const float*)d_in[20];
    const float* ln_b         = (const float*)d_in[21];
    const float* dec_W        = (const float*)d_in[22];

    // fold patch/phase projections + token projections
    prep_kernel<<<(PREP_TOTAL + 255) / 256, 256>>>(emb, patch_values, phase_embed,
                                                   sel_W, sel_b, bind_W1, bind_b1, succ_W1);

    spike_kernel<<<B_TOT / BM, TPB>>>(
        ids,
        sel_W + H * PP,                 // sel_W prev block (rows [H:2H))
        bind_W2, bind_b2,
        router_W, router_b,
        succ_b1, succ_W2, succ_b2,
        gate_W1, gate_b1, gate_W2, gate_b2,
        ln_g, ln_b, dec_W, (float*)d_out);
}